// round 15
// baseline (speedup 1.0000x reference)
#include <cuda_runtime.h>
#include <math.h>
#include <stdint.h>

// ---------------------------------------------------------------------------
// B=128, T=32, V=64, D=512.  score[128][128].
// sm_100 BASELINE target: mma.sync s8 (m16n8k32) + cp.async + ldmatrix.
// 2-level int8 row-scaled split:  x = s*(q1 + q2/254) + O(s/508)
//   score = sA[r]*sB[c]*( Σq1a*q1b + (Σq1a*q2b + Σq2a*q1b)/254 )
//   quant_prep:  per-row amax+quantize (prmt-packed, clamp-free) + scales;
//                masked-softmax weights
//   gemm_kernel: 128x128 tile/CTA (grid 64x32), 1 CTA/SM, warp tile 64x32
//                (smem traffic 128B/MMA vs 171 at the 2-CTA config; crossbar
//                demand drops below the 128 B/cyc peak), 2-stage cp.async,
//                fused scale+max epilogue -> score[a][b]
//   loss_kernel: 1024-thread smem-staged log-softmax -> scalar
// ---------------------------------------------------------------------------

#define NEG_BIG (-3.0e38f)

__device__ float g_wA[128 * 32];
__device__ float g_wB[128 * 64];
__device__ float g_score[128 * 128];
__device__ float g_sA[4096];
__device__ float g_sB[8192];

__device__ uint4 g_Aq1[4096 * 512 / 16];
__device__ uint4 g_Aq2[4096 * 512 / 16];
__device__ uint4 g_Bq1[8192 * 512 / 16];
__device__ uint4 g_Bq2[8192 * 512 / 16];

// ---------------- PTX helpers ----------------
__device__ __forceinline__ uint32_t smem_u32(const void* p) {
    uint32_t a;
    asm("{ .reg .u64 t; cvta.to.shared.u64 t, %1; cvt.u32.u64 %0, t; }" : "=r"(a) : "l"(p));
    return a;
}
__device__ __forceinline__ uint32_t prmt(uint32_t a, uint32_t b, uint32_t s) {
    uint32_t r;
    asm("prmt.b32 %0, %1, %2, %3;" : "=r"(r) : "r"(a), "r"(b), "r"(s));
    return r;
}
#define CP_ASYNC16(dst, src) asm volatile("cp.async.cg.shared.global [%0], [%1], 16;" :: "r"(dst), "l"(src))
#define CP_COMMIT()          asm volatile("cp.async.commit_group;" ::: "memory")
#define CP_WAIT1()           asm volatile("cp.async.wait_group 1;" ::: "memory")
#define CP_WAIT0()           asm volatile("cp.async.wait_group 0;" ::: "memory")
#define LDSM_X4(r0, r1, r2, r3, addr) \
    asm volatile("ldmatrix.sync.aligned.m8n8.x4.shared.b16 {%0,%1,%2,%3}, [%4];" \
        : "=r"(r0), "=r"(r1), "=r"(r2), "=r"(r3) : "r"(addr))
#define MMA_S8(d, a, b0, b1) \
    asm volatile("mma.sync.aligned.m16n8k32.row.col.s32.s8.s8.s32 " \
        "{%0,%1,%2,%3}, {%4,%5,%6,%7}, {%8,%9}, {%0,%1,%2,%3};" \
        : "+r"((d)[0]), "+r"((d)[1]), "+r"((d)[2]), "+r"((d)[3]) \
        : "r"((a)[0]), "r"((a)[1]), "r"((a)[2]), "r"((a)[3]), "r"(b0), "r"(b1))

// ---------------- input disambiguation ----------------
__device__ __forceinline__ bool looks_like_int_small(const unsigned* w, unsigned limit) {
    bool ok = true;
    #pragma unroll
    for (int i = 0; i < 8; i++) ok = ok && (w[i] <= limit);
    return ok;
}
__device__ __forceinline__ bool int_width64(const unsigned* w) {
    return (w[1] == 0u) && (w[3] == 0u) && (w[5] == 0u) && (w[7] == 0u);
}
__device__ __forceinline__ bool int_elem_nonzero(const unsigned* w, int i, bool w64) {
    return w64 ? ((w[2 * i] | w[2 * i + 1]) != 0u) : (w[i] != 0u);
}

// ---------------------------------------------------------------------------
// quant + prep.  Blocks [0,1536): one warp per feature row (12288 rows).
// Blocks [1536,1664): masked-softmax weights.
// ---------------------------------------------------------------------------
__global__ void __launch_bounds__(256)
quant_prep_kernel(const float* __restrict__ A, const float* __restrict__ B,
                  const void* q0, const void* q1p, const void* r0, const void* r1) {
    bool q0_tok = looks_like_int_small((const unsigned*)q0, 99999u);
    const unsigned* tokw = (const unsigned*)(q0_tok ? q0 : q1p);
    const float*    wtA  = (const float*)(q0_tok ? q1p : q0);
    bool tok64 = int_width64(tokw);
    bool r0_msk = looks_like_int_small((const unsigned*)r0, 1u);
    const unsigned* mskw = (const unsigned*)(r0_msk ? r0 : r1);
    const float*    wtB  = (const float*)(r0_msk ? r1 : r0);
    bool msk64 = int_width64(mskw);

    if (blockIdx.x >= 1536) {
        int row = blockIdx.x - 1536;
        int w = threadIdx.x >> 5, lane = threadIdx.x & 31;
        if (w == 0) {
            float m = int_elem_nonzero(tokw, row * 32 + lane, tok64) ? 1.f : 0.f;
            float x = (m > 0.f) ? wtA[row * 32 + lane] : NEG_BIG;
            float mx = x;
            #pragma unroll
            for (int o = 16; o; o >>= 1) mx = fmaxf(mx, __shfl_xor_sync(0xffffffffu, mx, o));
            float e = expf(x - mx), s = e;
            #pragma unroll
            for (int o = 16; o; o >>= 1) s += __shfl_xor_sync(0xffffffffu, s, o);
            g_wA[row * 32 + lane] = e / s;
        } else if (w == 1) {
            float m0 = int_elem_nonzero(mskw, row * 64 + lane, msk64) ? 1.f : 0.f;
            float m1 = int_elem_nonzero(mskw, row * 64 + lane + 32, msk64) ? 1.f : 0.f;
            float x0 = (m0 > 0.f) ? wtB[row * 64 + lane] : NEG_BIG;
            float x1 = (m1 > 0.f) ? wtB[row * 64 + lane + 32] : NEG_BIG;
            float mx = fmaxf(x0, x1);
            #pragma unroll
            for (int o = 16; o; o >>= 1) mx = fmaxf(mx, __shfl_xor_sync(0xffffffffu, mx, o));
            float e0 = expf(x0 - mx), e1 = expf(x1 - mx);
            float s = e0 + e1;
            #pragma unroll
            for (int o = 16; o; o >>= 1) s += __shfl_xor_sync(0xffffffffu, s, o);
            g_wB[row * 64 + lane] = e0 / s;
            g_wB[row * 64 + lane + 32] = e1 / s;
        }
        return;
    }

    int w = threadIdx.x >> 5, lane = threadIdx.x & 31;
    int row = blockIdx.x * 8 + w;
    bool isA = row < 4096;
    int rloc = isA ? row : row - 4096;
    const float* src = isA ? (A + (size_t)rloc * 512) : (B + (size_t)rloc * 512);
    float m = isA ? (int_elem_nonzero(tokw, rloc, tok64) ? 1.f : 0.f)
                  : (int_elem_nonzero(mskw, rloc, msk64) ? 1.f : 0.f);

    float v[16];
    #pragma unroll
    for (int i = 0; i < 4; i++) {
        float4 x = ((const float4*)src)[lane * 4 + i];
        v[i * 4 + 0] = x.x * m;
        v[i * 4 + 1] = x.y * m;
        v[i * 4 + 2] = x.z * m;
        v[i * 4 + 3] = x.w * m;
    }
    float amax = 0.f;
    #pragma unroll
    for (int i = 0; i < 16; i++) amax = fmaxf(amax, fabsf(v[i]));
    #pragma unroll
    for (int o = 16; o; o >>= 1) amax = fmaxf(amax, __shfl_xor_sync(0xffffffffu, amax, o));

    float sInv = (amax > 0.f) ? (127.f / amax) : 0.f;
    float s = amax * (1.f / 127.f);

    uint32_t p1[4], p2[4];
    #pragma unroll
    for (int g = 0; g < 4; g++) {
        uint32_t i1v[4], i2v[4];
        #pragma unroll
        for (int k = 0; k < 4; k++) {
            float x = v[g * 4 + k];
            float f1 = rintf(x * sInv);
            float r = fmaf(-f1, s, x);
            float f2 = rintf(r * 254.f * sInv);
            i1v[k] = (uint32_t)(int)f1;
            i2v[k] = (uint32_t)(int)f2;
        }
        p1[g] = prmt(prmt(i1v[0], i1v[1], 0x0040u), prmt(i1v[2], i1v[3], 0x0040u), 0x5410u);
        p2[g] = prmt(prmt(i2v[0], i2v[1], 0x0040u), prmt(i2v[2], i2v[3], 0x0040u), 0x5410u);
    }
    uint4 pk1 = make_uint4(p1[0], p1[1], p1[2], p1[3]);
    uint4 pk2 = make_uint4(p2[0], p2[1], p2[2], p2[3]);
    size_t idx = (size_t)rloc * 32 + lane;
    if (isA) { g_Aq1[idx] = pk1; g_Aq2[idx] = pk2; }
    else     { g_Bq1[idx] = pk1; g_Bq2[idx] = pk2; }
    if (lane == 0) { if (isA) g_sA[rloc] = s; else g_sB[rloc] = s; }
}

// ---------------------------------------------------------------------------
// GEMM: 128x128 tile/CTA, 1 CTA/SM, grid (64 n, 32 m).  256 threads,
// 8 warps = 2 m-bands x 4 n-bands, warp tile 64x32.  K=512 in 4 chunks of
// 128 int8 (SW128).  2-stage cp.async.  Stage (64 KB): AQ1|AQ2|BQ1|BQ2 16K each.
// ---------------------------------------------------------------------------
#define AQ1_OFF 0
#define AQ2_OFF 16384
#define BQ1_OFF 32768
#define BQ2_OFF 49152
#define STAGE_BYTES 65536
#define GEMM_SMEM (2 * STAGE_BYTES)

__device__ __forceinline__ void issue_copies(uint32_t sb, int m0, int n0, int ck, int tid) {
    const char* sA1 = (const char*)g_Aq1;
    const char* sA2 = (const char*)g_Aq2;
    const char* sB1 = (const char*)g_Bq1;
    const char* sB2 = (const char*)g_Bq2;
    #pragma unroll
    for (int i = 0; i < 4; i++) {              // AQ1: 128 rows x 8 units
        int u = tid + 256 * i, r = u >> 3, c = u & 7;
        uint32_t d = sb + AQ1_OFF + (uint32_t)(r * 128 + ((c ^ (r & 7)) * 16));
        CP_ASYNC16(d, sA1 + (size_t)(m0 + r) * 512 + ck * 128 + c * 16);
    }
    #pragma unroll
    for (int i = 0; i < 4; i++) {              // AQ2
        int u = tid + 256 * i, r = u >> 3, c = u & 7;
        uint32_t d = sb + AQ2_OFF + (uint32_t)(r * 128 + ((c ^ (r & 7)) * 16));
        CP_ASYNC16(d, sA2 + (size_t)(m0 + r) * 512 + ck * 128 + c * 16);
    }
    #pragma unroll
    for (int i = 0; i < 4; i++) {              // BQ1: 128 rows x 8 units
        int u = tid + 256 * i, r = u >> 3, c = u & 7;
        uint32_t d = sb + BQ1_OFF + (uint32_t)(r * 128 + ((c ^ (r & 7)) * 16));
        CP_ASYNC16(d, sB1 + (size_t)(n0 + r) * 512 + ck * 128 + c * 16);
    }
    #pragma unroll
    for (int i = 0; i < 4; i++) {              // BQ2
        int u = tid + 256 * i, r = u >> 3, c = u & 7;
        uint32_t d = sb + BQ2_OFF + (uint32_t)(r * 128 + ((c ^ (r & 7)) * 16));
        CP_ASYNC16(d, sB2 + (size_t)(n0 + r) * 512 + ck * 128 + c * 16);
    }
}

__global__ void __launch_bounds__(256, 1)
gemm_kernel() {
    extern __shared__ __align__(1024) char dyn[];
    uint32_t base = smem_u32(dyn);

    int tid = threadIdx.x;
    int w = tid >> 5, lane = tid & 31;
    int wm = w >> 2, wn = w & 3;               // 2 m-bands x 4 n-bands
    int q = lane >> 2, t4 = lane & 3;
    int m0 = blockIdx.y * 128, n0 = blockIdx.x * 128;

    int acc1[4][4][4], acc2[4][4][4];          // [mi][j][e], warp tile 64x32
    #pragma unroll
    for (int i = 0; i < 4; i++)
        #pragma unroll
        for (int j = 0; j < 4; j++)
            #pragma unroll
            for (int e = 0; e < 4; e++) { acc1[i][j][e] = 0; acc2[i][j][e] = 0; }

    issue_copies(base + 0 * STAGE_BYTES, m0, n0, 0, tid);
    CP_COMMIT();
    issue_copies(base + 1 * STAGE_BYTES, m0, n0, 1, tid);
    CP_COMMIT();

    int aRow = wm * 64 + ((lane >> 3) & 1) * 8 + (lane & 7);   // + mi*16
    int aUsel = lane >> 4;
    int bRow = wn * 32 + lane;

    for (int ck = 0; ck < 4; ck++) {
        uint32_t sb = base + (uint32_t)(ck & 1) * STAGE_BYTES;
        if (ck < 3) { CP_WAIT1(); } else { CP_WAIT0(); }
        __syncthreads();

        #pragma unroll
        for (int ks = 0; ks < 4; ks++) {
            int ub = ks * 2;
            uint32_t a1f[4][4], a2f[4][4];
            uint32_t b1u0[4], b1u1[4], b2u0[4], b2u1[4];
            // row&7 invariant under +16, so one swizzle unit for all mi
            uint32_t suA = (uint32_t)((ub + aUsel) ^ (aRow & 7)) * 16;
            uint32_t su0 = (uint32_t)(ub ^ (lane & 7)) * 16;
            uint32_t su1 = (uint32_t)((ub + 1) ^ (lane & 7)) * 16;
            uint32_t bd = sb + (uint32_t)(bRow * 128);

            #pragma unroll
            for (int mi = 0; mi < 4; mi++) {
                uint32_t ad = sb + (uint32_t)((aRow + mi * 16) * 128) + suA;
                LDSM_X4(a1f[mi][0], a1f[mi][1], a1f[mi][2], a1f[mi][3], ad + AQ1_OFF);
            }
            LDSM_X4(b1u0[0], b1u0[1], b1u0[2], b1u0[3], bd + BQ1_OFF + su0);
            LDSM_X4(b1u1[0], b1u1[1], b1u1[2], b1u1[3], bd + BQ1_OFF + su1);
            LDSM_X4(b2u0[0], b2u0[1], b2u0[2], b2u0[3], bd + BQ2_OFF + su0);
            LDSM_X4(b2u1[0], b2u1[1], b2u1[2], b2u1[3], bd + BQ2_OFF + su1);
            #pragma unroll
            for (int mi = 0; mi < 4; mi++) {
                uint32_t ad = sb + (uint32_t)((aRow + mi * 16) * 128) + suA;
                LDSM_X4(a2f[mi][0], a2f[mi][1], a2f[mi][2], a2f[mi][3], ad + AQ2_OFF);
            }

            // bank 1: a1*b1 (16 independent MMAs)
            #pragma unroll
            for (int mi = 0; mi < 4; mi++)
                #pragma unroll
                for (int j = 0; j < 4; j++)
                    MMA_S8(acc1[mi][j], a1f[mi], b1u0[j], b1u1[j]);
            // bank 2a: a1*b2
            #pragma unroll
            for (int mi = 0; mi < 4; mi++)
                #pragma unroll
                for (int j = 0; j < 4; j++)
                    MMA_S8(acc2[mi][j], a1f[mi], b2u0[j], b2u1[j]);
            // bank 2b: a2*b1
            #pragma unroll
            for (int mi = 0; mi < 4; mi++)
                #pragma unroll
                for (int j = 0; j < 4; j++)
                    MMA_S8(acc2[mi][j], a2f[mi], b1u0[j], b1u1[j]);
        }
        __syncthreads();
        if (ck + 2 < 4) {
            issue_copies(sb, m0, n0, ck + 2, tid);
            CP_COMMIT();
        }
    }

    // ---------------- fused epilogue (scales + max reductions) ----------------
    // element (mi,j,e): row = wm*64+mi*16+q+(e>>1)*8, col = wn*32+j*8+t4*2+(e&1)
    const float inv254 = 1.f / 254.f;
    float sAv[4][2];
    #pragma unroll
    for (int mi = 0; mi < 4; mi++)
        #pragma unroll
        for (int rh = 0; rh < 2; rh++)
            sAv[mi][rh] = g_sA[m0 + wm * 64 + mi * 16 + q + rh * 8];
    float sBv[4][2];
    #pragma unroll
    for (int j = 0; j < 4; j++)
        #pragma unroll
        for (int cp = 0; cp < 2; cp++)
            sBv[j][cp] = g_sB[n0 + wn * 32 + j * 8 + t4 * 2 + cp];

    // convert in place into acc1 (bit-cast floats) to keep register count flat
    #pragma unroll
    for (int mi = 0; mi < 4; mi++)
        #pragma unroll
        for (int j = 0; j < 4; j++)
            #pragma unroll
            for (int e = 0; e < 4; e++) {
                float v = __int2float_rn(acc1[mi][j][e]) + __int2float_rn(acc2[mi][j][e]) * inv254;
                acc1[mi][j][e] = __float_as_int(sAv[mi][e >> 1] * sBv[j][e & 1] * v);
            }
    #define SC(mi, j, e) __int_as_float(acc1[mi][j][e])

    float* rowred = (float*)dyn;          // [128 rows][4 wn]  = 512 floats
    float* colred = (float*)dyn + 512;    // [128 cols][4 a]   = 512 floats

    #pragma unroll
    for (int mi = 0; mi < 4; mi++) {
        #pragma unroll
        for (int rh = 0; rh < 2; rh++) {
            float m = fmaxf(SC(mi, 0, rh * 2), SC(mi, 0, rh * 2 + 1));
            #pragma unroll
            for (int j = 1; j < 4; j++)
                m = fmaxf(m, fmaxf(SC(mi, j, rh * 2), SC(mi, j, rh * 2 + 1)));
            m = fmaxf(m, __shfl_xor_sync(0xffffffffu, m, 1));
            m = fmaxf(m, __shfl_xor_sync(0xffffffffu, m, 2));
            if (t4 == 0) rowred[(wm * 64 + mi * 16 + q + rh * 8) * 4 + wn] = m;
        }
    }
    // col maxes per 32-row a-group: warp rows span a-groups 2*wm + asub
    #pragma unroll
    for (int j = 0; j < 4; j++) {
        #pragma unroll
        for (int cp = 0; cp < 2; cp++) {
            #pragma unroll
            for (int asub = 0; asub < 2; asub++) {
                int mb = asub * 2;
                float m = fmaxf(fmaxf(SC(mb, j, cp), SC(mb, j, cp + 2)),
                                fmaxf(SC(mb + 1, j, cp), SC(mb + 1, j, cp + 2)));
                m = fmaxf(m, __shfl_xor_sync(0xffffffffu, m, 4));
                m = fmaxf(m, __shfl_xor_sync(0xffffffffu, m, 8));
                m = fmaxf(m, __shfl_xor_sync(0xffffffffu, m, 16));
                if (q == 0) colred[(wn * 32 + j * 8 + t4 * 2 + cp) * 4 + (wm * 2 + asub)] = m;
            }
        }
    }
    __syncthreads();

    // 8 (a,b) pairs: warp w handles a = w>>1, b = w&1
    {
        int a = w >> 1, b = w & 1;
        int aG = blockIdx.y * 4 + a;
        int bG = blockIdx.x * 2 + b;
        float rf = fmaxf(fmaxf(rowred[(a * 32 + lane) * 4 + 2 * b],
                               rowred[(a * 32 + lane) * 4 + 2 * b + 1]),
                         NEG_BIG);
        float val = rf * g_wA[aG * 32 + lane];
        val += colred[(b * 64 + lane) * 4 + a]      * g_wB[bG * 64 + lane];
        val += colred[(b * 64 + lane + 32) * 4 + a] * g_wB[bG * 64 + lane + 32];
        #pragma unroll
        for (int o = 16; o; o >>= 1) val += __shfl_xor_sync(0xffffffffu, val, o);
        if (lane == 0) g_score[aG * 128 + bG] = 0.5f * val;
    }
    #undef SC
}

// ---------------------------------------------------------------------------
// loss: 1024 threads, smem-staged, strip-parallel.
// ---------------------------------------------------------------------------
#define LOSS_SMEM (16384 * 4 + 2048 * 4 + 256 * 4)
__global__ void __launch_bounds__(1024)
loss_kernel(const float* __restrict__ temp, float* __restrict__ out) {
    extern __shared__ __align__(16) float ls[];
    float* aux  = ls + 16384;
    float* aux2 = aux + 1024;
    float* red  = aux2 + 1024;
    int tid = threadIdx.x;
    float invT = 1.0f / temp[0];

    float4* d4 = (float4*)ls;
    const float4* s4 = (const float4*)g_score;
    for (int i = tid; i < 4096; i += 1024) d4[i] = s4[i];
    __syncthreads();

    int side = tid >> 9;
    int i = (tid >> 2) & 127;
    int st = tid & 3;

    float mx = NEG_BIG;
    #pragma unroll 8
    for (int j = 0; j < 32; j++) {
        float x = side ? ls[(st * 32 + j) * 128 + i] : ls[i * 128 + st * 32 + j];
        mx = fmaxf(mx, x);
    }
    aux[tid] = mx;
    __syncthreads();
    int gb = tid & ~3;
    float gmx = fmaxf(fmaxf(aux[gb], aux[gb + 1]), fmaxf(aux[gb + 2], aux[gb + 3]));

    float s = 0.f;
    #pragma unroll 8
    for (int j = 0; j < 32; j++) {
        float x = side ? ls[(st * 32 + j) * 128 + i] : ls[i * 128 + st * 32 + j];
        s += expf((x - gmx) * invT);
    }
    aux2[tid] = s;
    __syncthreads();
    if (st == 0) {
        float gs = aux2[gb] + aux2[gb + 1] + aux2[gb + 2] + aux2[gb + 3];
        float lse = gmx * invT + logf(gs);
        red[side * 128 + i] = lse - ls[i * 128 + i] * invT;
    }
    __syncthreads();
    for (int o = 128; o; o >>= 1) {
        if (tid < o) red[tid] += red[tid + o];
        __syncthreads();
    }
    if (tid == 0) out[0] = red[0] / 256.f;
}

// ---------------------------------------------------------------------------
extern "C" void kernel_launch(void* const* d_in, const int* in_sizes, int n_in,
                              void* d_out, int out_size) {
    (void)out_size;
    int order[7];
    for (int i = 0; i < 7 && i < n_in; i++) order[i] = i;
    for (int i = 1; i < 7; i++) {
        int o = order[i];
        long long s = in_sizes[o];
        int j = i - 1;
        while (j >= 0 && (long long)in_sizes[order[j]] > s) { order[j + 1] = order[j]; j--; }
        order[j + 1] = o;
    }
    const float* temp  = (const float*)d_in[order[0]];
    const void*  q0    = d_in[order[1]];
    const void*  q1    = d_in[order[2]];
    const void*  r0    = d_in[order[3]];
    const void*  r1    = d_in[order[4]];
    const float* featA = (const float*)d_in[order[5]];
    const float* featB = (const float*)d_in[order[6]];
    float* out = (float*)d_out;

    static bool attrSet = false;
    if (!attrSet) {
        cudaFuncSetAttribute(gemm_kernel, cudaFuncAttributeMaxDynamicSharedMemorySize, GEMM_SMEM);
        cudaFuncSetAttribute(loss_kernel, cudaFuncAttributeMaxDynamicSharedMemorySize, LOSS_SMEM);
        attrSet = true;
    }

    quant_prep_kernel<<<1664, 256>>>(featA, featB, q0, q1, r0, r1);
    gemm_kernel<<<dim3(64, 32), 256, GEMM_SMEM>>>();
    loss_kernel<<<1, 1024, LOSS_SMEM>>>(temp, out);
}

// round 17
// speedup vs baseline: 1.0006x; 1.0006x over previous
#include <cuda_runtime.h>
#include <math.h>
#include <stdint.h>

// ---------------------------------------------------------------------------
// B=128, T=32, V=64, D=512.  score[128][128].
// sm_100 BASELINE target: mma.sync s8 (m16n8k32) + cp.async + ldmatrix.
// 2-level int8 row-scaled split:  x = s*(q1 + q2/254) + O(s/508)
//   score = sA[r]*sB[c]*( Σq1a*q1b + (Σq1a*q2b + Σq2a*q1b)/254 )
//   quant_prep:  per-row amax+quantize (prmt-packed, clamp-free) + scales;
//                masked-softmax weights
//   gemm_kernel: 128x128 tile/CTA, 512 threads (16 warps = 4x4, warp tile
//                32x32 — same per-warp body as the proven 2-CTA config, same
//                latency hiding, but L2 traffic drops 35%), 1 CTA/SM,
//                2-stage cp.async, fused scale+max epilogue -> score[a][b]
//   loss_kernel: 1024-thread smem-staged log-softmax -> scalar
// ---------------------------------------------------------------------------

#define NEG_BIG (-3.0e38f)

__device__ float g_wA[128 * 32];
__device__ float g_wB[128 * 64];
__device__ float g_score[128 * 128];
__device__ float g_sA[4096];
__device__ float g_sB[8192];

__device__ uint4 g_Aq1[4096 * 512 / 16];
__device__ uint4 g_Aq2[4096 * 512 / 16];
__device__ uint4 g_Bq1[8192 * 512 / 16];
__device__ uint4 g_Bq2[8192 * 512 / 16];

// ---------------- PTX helpers ----------------
__device__ __forceinline__ uint32_t smem_u32(const void* p) {
    uint32_t a;
    asm("{ .reg .u64 t; cvta.to.shared.u64 t, %1; cvt.u32.u64 %0, t; }" : "=r"(a) : "l"(p));
    return a;
}
__device__ __forceinline__ uint32_t prmt(uint32_t a, uint32_t b, uint32_t s) {
    uint32_t r;
    asm("prmt.b32 %0, %1, %2, %3;" : "=r"(r) : "r"(a), "r"(b), "r"(s));
    return r;
}
#define CP_ASYNC16(dst, src) asm volatile("cp.async.cg.shared.global [%0], [%1], 16;" :: "r"(dst), "l"(src))
#define CP_COMMIT()          asm volatile("cp.async.commit_group;" ::: "memory")
#define CP_WAIT1()           asm volatile("cp.async.wait_group 1;" ::: "memory")
#define CP_WAIT0()           asm volatile("cp.async.wait_group 0;" ::: "memory")
#define LDSM_X4(r0, r1, r2, r3, addr) \
    asm volatile("ldmatrix.sync.aligned.m8n8.x4.shared.b16 {%0,%1,%2,%3}, [%4];" \
        : "=r"(r0), "=r"(r1), "=r"(r2), "=r"(r3) : "r"(addr))
#define MMA_S8(d, a, b0, b1) \
    asm volatile("mma.sync.aligned.m16n8k32.row.col.s32.s8.s8.s32 " \
        "{%0,%1,%2,%3}, {%4,%5,%6,%7}, {%8,%9}, {%0,%1,%2,%3};" \
        : "+r"((d)[0]), "+r"((d)[1]), "+r"((d)[2]), "+r"((d)[3]) \
        : "r"((a)[0]), "r"((a)[1]), "r"((a)[2]), "r"((a)[3]), "r"(b0), "r"(b1))

// ---------------- input disambiguation ----------------
__device__ __forceinline__ bool looks_like_int_small(const unsigned* w, unsigned limit) {
    bool ok = true;
    #pragma unroll
    for (int i = 0; i < 8; i++) ok = ok && (w[i] <= limit);
    return ok;
}
__device__ __forceinline__ bool int_width64(const unsigned* w) {
    return (w[1] == 0u) && (w[3] == 0u) && (w[5] == 0u) && (w[7] == 0u);
}
__device__ __forceinline__ bool int_elem_nonzero(const unsigned* w, int i, bool w64) {
    return w64 ? ((w[2 * i] | w[2 * i + 1]) != 0u) : (w[i] != 0u);
}

// ---------------------------------------------------------------------------
// quant + prep.  Blocks [0,1536): one warp per feature row (12288 rows).
// Blocks [1536,1664): masked-softmax weights.
// ---------------------------------------------------------------------------
__global__ void __launch_bounds__(256)
quant_prep_kernel(const float* __restrict__ A, const float* __restrict__ B,
                  const void* q0, const void* q1p, const void* r0, const void* r1) {
    bool q0_tok = looks_like_int_small((const unsigned*)q0, 99999u);
    const unsigned* tokw = (const unsigned*)(q0_tok ? q0 : q1p);
    const float*    wtA  = (const float*)(q0_tok ? q1p : q0);
    bool tok64 = int_width64(tokw);
    bool r0_msk = looks_like_int_small((const unsigned*)r0, 1u);
    const unsigned* mskw = (const unsigned*)(r0_msk ? r0 : r1);
    const float*    wtB  = (const float*)(r0_msk ? r1 : r0);
    bool msk64 = int_width64(mskw);

    if (blockIdx.x >= 1536) {
        int row = blockIdx.x - 1536;
        int w = threadIdx.x >> 5, lane = threadIdx.x & 31;
        if (w == 0) {
            float m = int_elem_nonzero(tokw, row * 32 + lane, tok64) ? 1.f : 0.f;
            float x = (m > 0.f) ? wtA[row * 32 + lane] : NEG_BIG;
            float mx = x;
            #pragma unroll
            for (int o = 16; o; o >>= 1) mx = fmaxf(mx, __shfl_xor_sync(0xffffffffu, mx, o));
            float e = expf(x - mx), s = e;
            #pragma unroll
            for (int o = 16; o; o >>= 1) s += __shfl_xor_sync(0xffffffffu, s, o);
            g_wA[row * 32 + lane] = e / s;
        } else if (w == 1) {
            float m0 = int_elem_nonzero(mskw, row * 64 + lane, msk64) ? 1.f : 0.f;
            float m1 = int_elem_nonzero(mskw, row * 64 + lane + 32, msk64) ? 1.f : 0.f;
            float x0 = (m0 > 0.f) ? wtB[row * 64 + lane] : NEG_BIG;
            float x1 = (m1 > 0.f) ? wtB[row * 64 + lane + 32] : NEG_BIG;
            float mx = fmaxf(x0, x1);
            #pragma unroll
            for (int o = 16; o; o >>= 1) mx = fmaxf(mx, __shfl_xor_sync(0xffffffffu, mx, o));
            float e0 = expf(x0 - mx), e1 = expf(x1 - mx);
            float s = e0 + e1;
            #pragma unroll
            for (int o = 16; o; o >>= 1) s += __shfl_xor_sync(0xffffffffu, s, o);
            g_wB[row * 64 + lane] = e0 / s;
            g_wB[row * 64 + lane + 32] = e1 / s;
        }
        return;
    }

    int w = threadIdx.x >> 5, lane = threadIdx.x & 31;
    int row = blockIdx.x * 8 + w;
    bool isA = row < 4096;
    int rloc = isA ? row : row - 4096;
    const float* src = isA ? (A + (size_t)rloc * 512) : (B + (size_t)rloc * 512);
    float m = isA ? (int_elem_nonzero(tokw, rloc, tok64) ? 1.f : 0.f)
                  : (int_elem_nonzero(mskw, rloc, msk64) ? 1.f : 0.f);

    float v[16];
    #pragma unroll
    for (int i = 0; i < 4; i++) {
        float4 x = ((const float4*)src)[lane * 4 + i];
        v[i * 4 + 0] = x.x * m;
        v[i * 4 + 1] = x.y * m;
        v[i * 4 + 2] = x.z * m;
        v[i * 4 + 3] = x.w * m;
    }
    float amax = 0.f;
    #pragma unroll
    for (int i = 0; i < 16; i++) amax = fmaxf(amax, fabsf(v[i]));
    #pragma unroll
    for (int o = 16; o; o >>= 1) amax = fmaxf(amax, __shfl_xor_sync(0xffffffffu, amax, o));

    float sInv = (amax > 0.f) ? (127.f / amax) : 0.f;
    float s = amax * (1.f / 127.f);

    uint32_t p1[4], p2[4];
    #pragma unroll
    for (int g = 0; g < 4; g++) {
        uint32_t i1v[4], i2v[4];
        #pragma unroll
        for (int k = 0; k < 4; k++) {
            float x = v[g * 4 + k];
            float f1 = rintf(x * sInv);
            float r = fmaf(-f1, s, x);
            float f2 = rintf(r * 254.f * sInv);
            i1v[k] = (uint32_t)(int)f1;
            i2v[k] = (uint32_t)(int)f2;
        }
        p1[g] = prmt(prmt(i1v[0], i1v[1], 0x0040u), prmt(i1v[2], i1v[3], 0x0040u), 0x5410u);
        p2[g] = prmt(prmt(i2v[0], i2v[1], 0x0040u), prmt(i2v[2], i2v[3], 0x0040u), 0x5410u);
    }
    uint4 pk1 = make_uint4(p1[0], p1[1], p1[2], p1[3]);
    uint4 pk2 = make_uint4(p2[0], p2[1], p2[2], p2[3]);
    size_t idx = (size_t)rloc * 32 + lane;
    if (isA) { g_Aq1[idx] = pk1; g_Aq2[idx] = pk2; }
    else     { g_Bq1[idx] = pk1; g_Bq2[idx] = pk2; }
    if (lane == 0) { if (isA) g_sA[rloc] = s; else g_sB[rloc] = s; }
}

// ---------------------------------------------------------------------------
// GEMM: 128x128 tile/CTA, 512 threads (16 warps = 4 m-bands x 4 n-bands,
// warp tile 32x32), 1 CTA/SM, grid (64 n, 32 m).  K=512 in 4 chunks of 128
// int8 (SW128).  2-stage cp.async.  Stage (64 KB): AQ1|AQ2|BQ1|BQ2 16K each.
// ---------------------------------------------------------------------------
#define AQ1_OFF 0
#define AQ2_OFF 16384
#define BQ1_OFF 32768
#define BQ2_OFF 49152
#define STAGE_BYTES 65536
#define GEMM_SMEM (2 * STAGE_BYTES)

__device__ __forceinline__ void issue_copies(uint32_t sb, int m0, int n0, int ck, int tid) {
    const char* sA1 = (const char*)g_Aq1;
    const char* sA2 = (const char*)g_Aq2;
    const char* sB1 = (const char*)g_Bq1;
    const char* sB2 = (const char*)g_Bq2;
    #pragma unroll
    for (int i = 0; i < 2; i++) {              // AQ1: 128 rows x 8 units = 1024
        int u = tid + 512 * i, r = u >> 3, c = u & 7;
        uint32_t d = sb + AQ1_OFF + (uint32_t)(r * 128 + ((c ^ (r & 7)) * 16));
        CP_ASYNC16(d, sA1 + (size_t)(m0 + r) * 512 + ck * 128 + c * 16);
    }
    #pragma unroll
    for (int i = 0; i < 2; i++) {              // AQ2
        int u = tid + 512 * i, r = u >> 3, c = u & 7;
        uint32_t d = sb + AQ2_OFF + (uint32_t)(r * 128 + ((c ^ (r & 7)) * 16));
        CP_ASYNC16(d, sA2 + (size_t)(m0 + r) * 512 + ck * 128 + c * 16);
    }
    #pragma unroll
    for (int i = 0; i < 2; i++) {              // BQ1: 128 rows x 8 units
        int u = tid + 512 * i, r = u >> 3, c = u & 7;
        uint32_t d = sb + BQ1_OFF + (uint32_t)(r * 128 + ((c ^ (r & 7)) * 16));
        CP_ASYNC16(d, sB1 + (size_t)(n0 + r) * 512 + ck * 128 + c * 16);
    }
    #pragma unroll
    for (int i = 0; i < 2; i++) {              // BQ2
        int u = tid + 512 * i, r = u >> 3, c = u & 7;
        uint32_t d = sb + BQ2_OFF + (uint32_t)(r * 128 + ((c ^ (r & 7)) * 16));
        CP_ASYNC16(d, sB2 + (size_t)(n0 + r) * 512 + ck * 128 + c * 16);
    }
}

__global__ void __launch_bounds__(512, 1)
gemm_kernel() {
    extern __shared__ __align__(1024) char dyn[];
    uint32_t base = smem_u32(dyn);

    int tid = threadIdx.x;
    int w = tid >> 5, lane = tid & 31;
    int wm = w >> 2, wn = w & 3;               // 4 m-bands x 4 n-bands
    int q = lane >> 2, t4 = lane & 3;
    int m0 = blockIdx.y * 128, n0 = blockIdx.x * 128;

    int acc1[2][4][4], acc2[2][4][4];          // warp tile 32x32
    #pragma unroll
    for (int i = 0; i < 2; i++)
        #pragma unroll
        for (int j = 0; j < 4; j++)
            #pragma unroll
            for (int e = 0; e < 4; e++) { acc1[i][j][e] = 0; acc2[i][j][e] = 0; }

    issue_copies(base + 0 * STAGE_BYTES, m0, n0, 0, tid);
    CP_COMMIT();
    issue_copies(base + 1 * STAGE_BYTES, m0, n0, 1, tid);
    CP_COMMIT();

    int aRow = wm * 32 + ((lane >> 3) & 1) * 8 + (lane & 7);   // + mi*16
    int aUsel = lane >> 4;
    int bRow = wn * 32 + lane;

    for (int ck = 0; ck < 4; ck++) {
        uint32_t sb = base + (uint32_t)(ck & 1) * STAGE_BYTES;
        if (ck < 3) { CP_WAIT1(); } else { CP_WAIT0(); }
        __syncthreads();

        #pragma unroll
        for (int ks = 0; ks < 4; ks++) {
            int ub = ks * 2;
            uint32_t a1f[2][4], a2f[2][4];
            uint32_t b1u0[4], b1u1[4], b2u0[4], b2u1[4];
            uint32_t suA = (uint32_t)((ub + aUsel) ^ (aRow & 7)) * 16;
            uint32_t su0 = (uint32_t)(ub ^ (lane & 7)) * 16;
            uint32_t su1 = (uint32_t)((ub + 1) ^ (lane & 7)) * 16;
            uint32_t bd = sb + (uint32_t)(bRow * 128);
            uint32_t ad0 = sb + (uint32_t)(aRow * 128) + suA;
            uint32_t ad1 = sb + (uint32_t)((aRow + 16) * 128) + suA;

            LDSM_X4(a1f[0][0], a1f[0][1], a1f[0][2], a1f[0][3], ad0 + AQ1_OFF);
            LDSM_X4(a1f[1][0], a1f[1][1], a1f[1][2], a1f[1][3], ad1 + AQ1_OFF);
            LDSM_X4(b1u0[0], b1u0[1], b1u0[2], b1u0[3], bd + BQ1_OFF + su0);
            LDSM_X4(b1u1[0], b1u1[1], b1u1[2], b1u1[3], bd + BQ1_OFF + su1);
            LDSM_X4(b2u0[0], b2u0[1], b2u0[2], b2u0[3], bd + BQ2_OFF + su0);
            LDSM_X4(b2u1[0], b2u1[1], b2u1[2], b2u1[3], bd + BQ2_OFF + su1);
            LDSM_X4(a2f[0][0], a2f[0][1], a2f[0][2], a2f[0][3], ad0 + AQ2_OFF);
            LDSM_X4(a2f[1][0], a2f[1][1], a2f[1][2], a2f[1][3], ad1 + AQ2_OFF);

            #pragma unroll
            for (int mi = 0; mi < 2; mi++)
                #pragma unroll
                for (int j = 0; j < 4; j++)
                    MMA_S8(acc1[mi][j], a1f[mi], b1u0[j], b1u1[j]);
            #pragma unroll
            for (int mi = 0; mi < 2; mi++)
                #pragma unroll
                for (int j = 0; j < 4; j++)
                    MMA_S8(acc2[mi][j], a1f[mi], b2u0[j], b2u1[j]);
            #pragma unroll
            for (int mi = 0; mi < 2; mi++)
                #pragma unroll
                for (int j = 0; j < 4; j++)
                    MMA_S8(acc2[mi][j], a2f[mi], b1u0[j], b1u1[j]);
        }
        __syncthreads();
        if (ck + 2 < 4) {
            issue_copies(sb, m0, n0, ck + 2, tid);
            CP_COMMIT();
        }
    }

    // ---------------- fused epilogue (scales + max reductions) ----------------
    // element (mi,j,e): row = wm*32+mi*16+q+(e>>1)*8, col = wn*32+j*8+t4*2+(e&1)
    const float inv254 = 1.f / 254.f;
    float sAv[2][2];
    #pragma unroll
    for (int mi = 0; mi < 2; mi++)
        #pragma unroll
        for (int rh = 0; rh < 2; rh++)
            sAv[mi][rh] = g_sA[m0 + wm * 32 + mi * 16 + q + rh * 8];
    float sBv[4][2];
    #pragma unroll
    for (int j = 0; j < 4; j++)
        #pragma unroll
        for (int cp = 0; cp < 2; cp++)
            sBv[j][cp] = g_sB[n0 + wn * 32 + j * 8 + t4 * 2 + cp];

    float sc[2][4][4];
    #pragma unroll
    for (int mi = 0; mi < 2; mi++)
        #pragma unroll
        for (int j = 0; j < 4; j++)
            #pragma unroll
            for (int e = 0; e < 4; e++) {
                float v = __int2float_rn(acc1[mi][j][e]) + __int2float_rn(acc2[mi][j][e]) * inv254;
                sc[mi][j][e] = sAv[mi][e >> 1] * sBv[j][e & 1] * v;
            }

    float* rowred = (float*)dyn;          // [128 rows][4 wn]  = 512 floats
    float* colred = (float*)dyn + 512;    // [128 cols][4 a]   = 512 floats

    #pragma unroll
    for (int mi = 0; mi < 2; mi++) {
        #pragma unroll
        for (int rh = 0; rh < 2; rh++) {
            float m = fmaxf(sc[mi][0][rh * 2], sc[mi][0][rh * 2 + 1]);
            #pragma unroll
            for (int j = 1; j < 4; j++)
                m = fmaxf(m, fmaxf(sc[mi][j][rh * 2], sc[mi][j][rh * 2 + 1]));
            m = fmaxf(m, __shfl_xor_sync(0xffffffffu, m, 1));
            m = fmaxf(m, __shfl_xor_sync(0xffffffffu, m, 2));
            if (t4 == 0) rowred[(wm * 32 + mi * 16 + q + rh * 8) * 4 + wn] = m;
        }
    }
    // col maxes: warp's 32 rows == exactly text a-group wm
    #pragma unroll
    for (int j = 0; j < 4; j++) {
        #pragma unroll
        for (int cp = 0; cp < 2; cp++) {
            float m = fmaxf(fmaxf(sc[0][j][cp], sc[0][j][cp + 2]),
                            fmaxf(sc[1][j][cp], sc[1][j][cp + 2]));
            m = fmaxf(m, __shfl_xor_sync(0xffffffffu, m, 4));
            m = fmaxf(m, __shfl_xor_sync(0xffffffffu, m, 8));
            m = fmaxf(m, __shfl_xor_sync(0xffffffffu, m, 16));
            if (q == 0) colred[(wn * 32 + j * 8 + t4 * 2 + cp) * 4 + wm] = m;
        }
    }
    __syncthreads();

    // 8 (a,b) pairs: warps 0..7, a = w>>1, b = w&1
    if (w < 8) {
        int a = w >> 1, b = w & 1;
        int aG = blockIdx.y * 4 + a;
        int bG = blockIdx.x * 2 + b;
        int rr = (a * 32 + lane) * 4;
        // b-half = two 32-col bands: wn = 2b and 2b+1
        float rf = fmaxf(rowred[rr + 2 * b], rowred[rr + 2 * b + 1]);
        float val = rf * g_wA[aG * 32 + lane];
        val += colred[(b * 64 + lane) * 4 + a]      * g_wB[bG * 64 + lane];
        val += colred[(b * 64 + lane + 32) * 4 + a] * g_wB[bG * 64 + lane + 32];
        #pragma unroll
        for (int o = 16; o; o >>= 1) val += __shfl_xor_sync(0xffffffffu, val, o);
        if (lane == 0) g_score[aG * 128 + bG] = 0.5f * val;
    }
}

// ---------------------------------------------------------------------------
// loss: 1024 threads, smem-staged, strip-parallel.
// ---------------------------------------------------------------------------
#define LOSS_SMEM (16384 * 4 + 2048 * 4 + 256 * 4)
__global__ void __launch_bounds__(1024)
loss_kernel(const float* __restrict__ temp, float* __restrict__ out) {
    extern __shared__ __align__(16) float ls[];
    float* aux  = ls + 16384;
    float* aux2 = aux + 1024;
    float* red  = aux2 + 1024;
    int tid = threadIdx.x;
    float invT = 1.0f / temp[0];

    float4* d4 = (float4*)ls;
    const float4* s4 = (const float4*)g_score;
    for (int i = tid; i < 4096; i += 1024) d4[i] = s4[i];
    __syncthreads();

    int side = tid >> 9;
    int i = (tid >> 2) & 127;
    int st = tid & 3;

    float mx = NEG_BIG;
    #pragma unroll 8
    for (int j = 0; j < 32; j++) {
        float x = side ? ls[(st * 32 + j) * 128 + i] : ls[i * 128 + st * 32 + j];
        mx = fmaxf(mx, x);
    }
    aux[tid] = mx;
    __syncthreads();
    int gb = tid & ~3;
    float gmx = fmaxf(fmaxf(aux[gb], aux[gb + 1]), fmaxf(aux[gb + 2], aux[gb + 3]));

    float s = 0.f;
    #pragma unroll 8
    for (int j = 0; j < 32; j++) {
        float x = side ? ls[(st * 32 + j) * 128 + i] : ls[i * 128 + st * 32 + j];
        s += expf((x - gmx) * invT);
    }
    aux2[tid] = s;
    __syncthreads();
    if (st == 0) {
        float gs = aux2[gb] + aux2[gb + 1] + aux2[gb + 2] + aux2[gb + 3];
        float lse = gmx * invT + logf(gs);
        red[side * 128 + i] = lse - ls[i * 128 + i] * invT;
    }
    __syncthreads();
    for (int o = 128; o; o >>= 1) {
        if (tid < o) red[tid] += red[tid + o];
        __syncthreads();
    }
    if (tid == 0) out[0] = red[0] / 256.f;
}

// ---------------------------------------------------------------------------
extern "C" void kernel_launch(void* const* d_in, const int* in_sizes, int n_in,
                              void* d_out, int out_size) {
    (void)out_size;
    int order[7];
    for (int i = 0; i < 7 && i < n_in; i++) order[i] = i;
    for (int i = 1; i < 7; i++) {
        int o = order[i];
        long long s = in_sizes[o];
        int j = i - 1;
        while (j >= 0 && (long long)in_sizes[order[j]] > s) { order[j + 1] = order[j]; j--; }
        order[j + 1] = o;
    }
    const float* temp  = (const float*)d_in[order[0]];
    const void*  q0    = d_in[order[1]];
    const void*  q1    = d_in[order[2]];
    const void*  r0    = d_in[order[3]];
    const void*  r1    = d_in[order[4]];
    const float* featA = (const float*)d_in[order[5]];
    const float* featB = (const float*)d_in[order[6]];
    float* out = (float*)d_out;

    static bool attrSet = false;
    if (!attrSet) {
        cudaFuncSetAttribute(gemm_kernel, cudaFuncAttributeMaxDynamicSharedMemorySize, GEMM_SMEM);
        cudaFuncSetAttribute(loss_kernel, cudaFuncAttributeMaxDynamicSharedMemorySize, LOSS_SMEM);
        attrSet = true;
    }

    quant_prep_kernel<<<1664, 256>>>(featA, featB, q0, q1, r0, r1);
    gemm_kernel<<<dim3(64, 32), 512, GEMM_SMEM>>>();
    loss_kernel<<<1, 1024, LOSS_SMEM>>>(temp, out);
}